// round 1
// baseline (speedup 1.0000x reference)
#include <cuda_runtime.h>
#include <math.h>

#define TT 2048
#define CC 2048
#define NH 32
#define NKVH 8
#define HD 64

// Scratch (device globals — no allocation allowed)
__device__ float g_q[TT * CC];
__device__ float g_k[TT * NKVH * HD];
__device__ float g_v[TT * NKVH * HD];
__device__ float g_att[TT * CC];

// ---------------------------------------------------------------------------
// GEMM: C[M,N] = A[M,K] @ B[K,N] + bias[N]
// 64x64 block tile, BK=16, 256 threads, 4x4 per thread.
// ---------------------------------------------------------------------------
__global__ void gemm_bias_kernel(const float* __restrict__ A,
                                 const float* __restrict__ B,
                                 const float* __restrict__ bias,
                                 float* __restrict__ C,
                                 int M, int N, int K) {
    __shared__ float As[64][17];   // [row][k], padded
    __shared__ float Bs[16][64];   // [k][col]
    const int tid = threadIdx.x;
    const int tr = tid >> 4;       // 0..15
    const int tc = tid & 15;       // 0..15
    const int row0 = blockIdx.y * 64;
    const int col0 = blockIdx.x * 64;

    float acc[4][4] = {};

    for (int k0 = 0; k0 < K; k0 += 16) {
        // Load A tile: 64x16, coalesced along k
        #pragma unroll
        for (int s = 0; s < 4; s++) {
            int i  = tid + s * 256;
            int rr = i >> 4;
            int cc = i & 15;
            As[rr][cc] = A[(size_t)(row0 + rr) * K + k0 + cc];
        }
        // Load B tile: 16x64, coalesced along n
        #pragma unroll
        for (int s = 0; s < 4; s++) {
            int i  = tid + s * 256;
            int rr = i >> 6;
            int cc = i & 63;
            Bs[rr][cc] = B[(size_t)(k0 + rr) * N + col0 + cc];
        }
        __syncthreads();

        #pragma unroll
        for (int kk = 0; kk < 16; kk++) {
            float4 b4 = *reinterpret_cast<const float4*>(&Bs[kk][tc * 4]);
            float b[4] = {b4.x, b4.y, b4.z, b4.w};
            float a[4];
            #pragma unroll
            for (int i = 0; i < 4; i++) a[i] = As[tr * 4 + i][kk];
            #pragma unroll
            for (int i = 0; i < 4; i++)
                #pragma unroll
                for (int j = 0; j < 4; j++)
                    acc[i][j] = fmaf(a[i], b[j], acc[i][j]);
        }
        __syncthreads();
    }

    #pragma unroll
    for (int i = 0; i < 4; i++) {
        int r = row0 + tr * 4 + i;
        #pragma unroll
        for (int j = 0; j < 4; j++) {
            int c = col0 + tc * 4 + j;
            C[(size_t)r * N + c] = acc[i][j] + bias[c];
        }
    }
}

// ---------------------------------------------------------------------------
// Fused RMSNorm (over head_dim=64) + RoPE. One warp per (t, head).
// Data layout: [T, nh, 64] contiguous. cos/sin: [T, 32].
// ---------------------------------------------------------------------------
__global__ void norm_rope_kernel(float* __restrict__ d,
                                 const float* __restrict__ w,
                                 const float* __restrict__ fcos,
                                 const float* __restrict__ fsin,
                                 int nh) {
    const int gw   = (blockIdx.x * blockDim.x + threadIdx.x) >> 5;
    const int lane = threadIdx.x & 31;
    const int t = gw / nh;
    const int h = gw % nh;

    float* row = d + ((size_t)t * nh + h) * 64;
    float2 xv = reinterpret_cast<float2*>(row)[lane];

    float ss = xv.x * xv.x + xv.y * xv.y;
    #pragma unroll
    for (int off = 16; off; off >>= 1)
        ss += __shfl_xor_sync(0xffffffffu, ss, off);

    float inv = rsqrtf(ss * (1.0f / 64.0f) + 1e-5f);

    float2 wv = reinterpret_cast<const float2*>(w)[lane];
    float a = xv.x * inv * wv.x;
    float b = xv.y * inv * wv.y;

    float c = fcos[t * 32 + lane];
    float s = fsin[t * 32 + lane];

    float2 out;
    out.x = a * c - b * s;
    out.y = a * s + b * c;
    reinterpret_cast<float2*>(row)[lane] = out;
}

// ---------------------------------------------------------------------------
// Flash-attention style causal attention.
// Block = (64 queries) x (one head). 256 threads, 4x4 register tiles.
// q: [T, 32*64], k/v: [T, 8*64], o: [T, 32*64]. GQA: kv head = h/4.
// Dynamic smem: Qs + Ks + Vs + Ps = 4 * 64*64*4 = 64 KB.
// ---------------------------------------------------------------------------
__global__ void attn_kernel(const float* __restrict__ q,
                            const float* __restrict__ k,
                            const float* __restrict__ v,
                            float* __restrict__ o) {
    const int qb  = gridDim.x - 1 - blockIdx.x;  // long blocks launch first
    const int h   = blockIdx.y;
    const int kvh = h >> 2;
    const int tid = threadIdx.x;
    const int tr  = tid >> 4;
    const int tc  = tid & 15;

    extern __shared__ float sm[];
    float* Qs = sm;             // Qs[d*64 + i]
    float* Ks = sm + 4096;      // Ks[d*64 + j]
    float* Vs = sm + 8192;      // Vs[j*64 + d]
    float* Ps = sm + 12288;     // Ps[j*64 + i]

    const int q0 = qb * 64;

    // Load Q tile transposed: Qs[d][i] = q[q0+i][h*64+d]
    for (int idx = tid; idx < 4096; idx += 256) {
        int i = idx >> 6;
        int d = idx & 63;
        Qs[d * 64 + i] = q[(size_t)(q0 + i) * (NH * HD) + h * HD + d];
    }

    float m[4], l[4], acc[4][4];
    #pragma unroll
    for (int i = 0; i < 4; i++) {
        m[i] = -1e30f;
        l[i] = 0.0f;
        #pragma unroll
        for (int j = 0; j < 4; j++) acc[i][j] = 0.0f;
    }

    for (int kb = 0; kb <= qb; kb++) {
        const int k0 = kb * 64;
        __syncthreads();  // prev PV reads & Qs load done before overwriting tiles
        for (int idx = tid; idx < 4096; idx += 256) {
            int j = idx >> 6;
            int d = idx & 63;
            size_t base = (size_t)(k0 + j) * (NKVH * HD) + kvh * HD + d;
            Ks[d * 64 + j] = k[base];
            Vs[j * 64 + d] = v[base];
        }
        __syncthreads();

        // S = Q K^T (64x64, 4x4 per thread)
        float S[4][4] = {};
        #pragma unroll 16
        for (int d = 0; d < 64; d++) {
            float4 a4 = *reinterpret_cast<const float4*>(&Qs[d * 64 + tr * 4]);
            float4 b4 = *reinterpret_cast<const float4*>(&Ks[d * 64 + tc * 4]);
            float a[4] = {a4.x, a4.y, a4.z, a4.w};
            float b[4] = {b4.x, b4.y, b4.z, b4.w};
            #pragma unroll
            for (int i = 0; i < 4; i++)
                #pragma unroll
                for (int j = 0; j < 4; j++)
                    S[i][j] = fmaf(a[i], b[j], S[i][j]);
        }

        // scale + causal mask (reference adds -1e9 to scaled scores)
        const bool diag = (kb == qb);
        float mi[4];
        #pragma unroll
        for (int i = 0; i < 4; i++) {
            #pragma unroll
            for (int j = 0; j < 4; j++) {
                float s = S[i][j] * 0.125f;
                if (diag && (tc * 4 + j > tr * 4 + i)) s -= 1e9f;
                S[i][j] = s;
            }
            mi[i] = fmaxf(fmaxf(S[i][0], S[i][1]), fmaxf(S[i][2], S[i][3]));
        }
        // row-wise reduce across the 16 lanes owning this query row
        #pragma unroll
        for (int off = 8; off; off >>= 1)
            #pragma unroll
            for (int i = 0; i < 4; i++)
                mi[i] = fmaxf(mi[i], __shfl_xor_sync(0xffffffffu, mi[i], off));

        float fac[4], rs[4];
        #pragma unroll
        for (int i = 0; i < 4; i++) {
            float mnew = fmaxf(m[i], mi[i]);
            fac[i] = __expf(m[i] - mnew);
            m[i] = mnew;
            float r = 0.0f;
            #pragma unroll
            for (int j = 0; j < 4; j++) {
                float p = __expf(S[i][j] - mnew);
                S[i][j] = p;
                r += p;
            }
            rs[i] = r;
        }
        #pragma unroll
        for (int off = 8; off; off >>= 1)
            #pragma unroll
            for (int i = 0; i < 4; i++)
                rs[i] += __shfl_xor_sync(0xffffffffu, rs[i], off);

        #pragma unroll
        for (int i = 0; i < 4; i++) {
            l[i] = l[i] * fac[i] + rs[i];
            #pragma unroll
            for (int j = 0; j < 4; j++) acc[i][j] *= fac[i];
        }

        // Write P transposed: Ps[key j][query i]
        #pragma unroll
        for (int j = 0; j < 4; j++)
            #pragma unroll
            for (int i = 0; i < 4; i++)
                Ps[(tc * 4 + j) * 64 + tr * 4 + i] = S[i][j];
        __syncthreads();

        // O += P @ V  (over 64 keys)
        #pragma unroll 16
        for (int j = 0; j < 64; j++) {
            float4 a4 = *reinterpret_cast<const float4*>(&Ps[j * 64 + tr * 4]);
            float4 b4 = *reinterpret_cast<const float4*>(&Vs[j * 64 + tc * 4]);
            float a[4] = {a4.x, a4.y, a4.z, a4.w};
            float b[4] = {b4.x, b4.y, b4.z, b4.w};
            #pragma unroll
            for (int i = 0; i < 4; i++)
                #pragma unroll
                for (int dd = 0; dd < 4; dd++)
                    acc[i][dd] = fmaf(a[i], b[dd], acc[i][dd]);
        }
    }

    // Epilogue: normalize and store to [T, H*64]
    #pragma unroll
    for (int i = 0; i < 4; i++) {
        float invl = 1.0f / l[i];
        size_t rbase = (size_t)(q0 + tr * 4 + i) * (NH * HD) + h * HD + tc * 4;
        #pragma unroll
        for (int dd = 0; dd < 4; dd++)
            o[rbase + dd] = acc[i][dd] * invl;
    }
}

// ---------------------------------------------------------------------------
extern "C" void kernel_launch(void* const* d_in, const int* in_sizes, int n_in,
                              void* d_out, int out_size) {
    const float* x    = (const float*)d_in[0];
    const float* fcos = (const float*)d_in[1];
    const float* fsin = (const float*)d_in[2];
    // d_in[3] = mask (causal, replicated in-kernel)
    const float* wq  = (const float*)d_in[4];
    const float* wqb = (const float*)d_in[5];
    const float* wk  = (const float*)d_in[6];
    const float* wkb = (const float*)d_in[7];
    const float* wv  = (const float*)d_in[8];
    const float* wvb = (const float*)d_in[9];
    const float* wo  = (const float*)d_in[10];
    const float* wob = (const float*)d_in[11];
    const float* qnw = (const float*)d_in[12];
    const float* knw = (const float*)d_in[13];
    float* out = (float*)d_out;

    float *q, *k, *v, *att;
    cudaGetSymbolAddress((void**)&q,   g_q);
    cudaGetSymbolAddress((void**)&k,   g_k);
    cudaGetSymbolAddress((void**)&v,   g_v);
    cudaGetSymbolAddress((void**)&att, g_att);

    // QKV projections
    gemm_bias_kernel<<<dim3(CC / 64, TT / 64), 256>>>(x, wq, wqb, q, TT, CC, CC);
    gemm_bias_kernel<<<dim3((NKVH * HD) / 64, TT / 64), 256>>>(x, wk, wkb, k, TT, NKVH * HD, CC);
    gemm_bias_kernel<<<dim3((NKVH * HD) / 64, TT / 64), 256>>>(x, wv, wvb, v, TT, NKVH * HD, CC);

    // RMSNorm + RoPE (one warp per (t, head); 256 threads = 8 warps per block)
    norm_rope_kernel<<<(TT * NH) / 8, 256>>>(q, qnw, fcos, fsin, NH);
    norm_rope_kernel<<<(TT * NKVH) / 8, 256>>>(k, knw, fcos, fsin, NKVH);

    // Attention
    cudaFuncSetAttribute(attn_kernel, cudaFuncAttributeMaxDynamicSharedMemorySize, 65536);
    attn_kernel<<<dim3(TT / 64, NH), 256, 65536>>>(q, k, v, att);

    // Output projection
    gemm_bias_kernel<<<dim3(CC / 64, TT / 64), 256>>>(att, wo, wob, out, TT, CC, CC);
}

// round 5
// speedup vs baseline: 1.6385x; 1.6385x over previous
#include <cuda_runtime.h>
#include <cuda_bf16.h>
#include <stdint.h>
#include <math.h>

#define TT 2048
#define CC 2048
#define NH 32
#define NKVH 8
#define HD 64
#define KDIM 2048

// ---------------- scratch (device globals; no allocation allowed) ----------
__device__ float g_q[TT * CC];
__device__ float g_k[TT * NKVH * HD];
__device__ float g_v[TT * NKVH * HD];
__device__ float g_att[TT * CC];

__device__ __nv_bfloat16 g_xh[TT * CC],  g_xl[TT * CC];
__device__ __nv_bfloat16 g_ah[TT * CC],  g_al[TT * CC];
__device__ __nv_bfloat16 g_wqh[CC * CC], g_wql[CC * CC];
__device__ __nv_bfloat16 g_wkh[512 * CC], g_wkl[512 * CC];
__device__ __nv_bfloat16 g_wvh[512 * CC], g_wvl[512 * CC];
__device__ __nv_bfloat16 g_woh[CC * CC], g_wol[CC * CC];

// ---------------- helpers ----------------------------------------------
__device__ __forceinline__ uint32_t smem_u32(const void* p) {
    uint32_t a;
    asm("{ .reg .u64 t; cvta.to.shared.u64 t, %1; cvt.u32.u64 %0, t; }" : "=r"(a) : "l"(p));
    return a;
}
__device__ __forceinline__ void cp_async16(uint32_t s, const void* g) {
    asm volatile("cp.async.cg.shared.global [%0], [%1], 16;" :: "r"(s), "l"(g) : "memory");
}
__device__ __forceinline__ void cp_commit_wait() {
    asm volatile("cp.async.commit_group;" ::: "memory");
    asm volatile("cp.async.wait_group 0;" ::: "memory");
}
__device__ __forceinline__ void ldsm_x4(uint32_t* r, uint32_t a) {
    asm volatile("ldmatrix.sync.aligned.m8n8.x4.shared.b16 {%0,%1,%2,%3}, [%4];"
                 : "=r"(r[0]), "=r"(r[1]), "=r"(r[2]), "=r"(r[3]) : "r"(a));
}
__device__ __forceinline__ void ldsm_x2(uint32_t* r, uint32_t a) {
    asm volatile("ldmatrix.sync.aligned.m8n8.x2.shared.b16 {%0,%1}, [%2];"
                 : "=r"(r[0]), "=r"(r[1]) : "r"(a));
}
__device__ __forceinline__ void mma_bf16(float* d, const uint32_t* a, const uint32_t* b) {
    asm volatile(
        "mma.sync.aligned.m16n8k16.row.col.f32.bf16.bf16.f32 "
        "{%0,%1,%2,%3}, {%4,%5,%6,%7}, {%8,%9}, {%0,%1,%2,%3};"
        : "+f"(d[0]), "+f"(d[1]), "+f"(d[2]), "+f"(d[3])
        : "r"(a[0]), "r"(a[1]), "r"(a[2]), "r"(a[3]), "r"(b[0]), "r"(b[1]));
}

// ---------------- split kernels ---------------------------------------------
struct alignas(8) bf4 { __nv_bfloat16 v[4]; };

__global__ void split_ew(const float* __restrict__ x, __nv_bfloat16* __restrict__ h,
                         __nv_bfloat16* __restrict__ l, int n4) {
    int i = blockIdx.x * blockDim.x + threadIdx.x;
    if (i >= n4) return;
    float4 v = reinterpret_cast<const float4*>(x)[i];
    float f[4] = {v.x, v.y, v.z, v.w};
    bf4 hh, ll;
    #pragma unroll
    for (int j = 0; j < 4; j++) {
        hh.v[j] = __float2bfloat16(f[j]);
        ll.v[j] = __float2bfloat16(f[j] - __bfloat162float(hh.v[j]));
    }
    reinterpret_cast<bf4*>(h)[i] = hh;
    reinterpret_cast<bf4*>(l)[i] = ll;
}

// W [K,N] fp32 -> Th/Tl [N,K] bf16
__global__ void transpose_split(const float* __restrict__ W, __nv_bfloat16* __restrict__ Th,
                                __nv_bfloat16* __restrict__ Tl, int K, int N) {
    __shared__ float t[32][33];
    int n0 = blockIdx.x * 32, k0 = blockIdx.y * 32;
    int tx = threadIdx.x, ty = threadIdx.y;   // (32, 8)
    #pragma unroll
    for (int i = ty; i < 32; i += 8)
        t[i][tx] = W[(size_t)(k0 + i) * N + n0 + tx];
    __syncthreads();
    #pragma unroll
    for (int i = ty; i < 32; i += 8) {
        float v = t[tx][i];
        __nv_bfloat16 h = __float2bfloat16(v);
        __nv_bfloat16 l = __float2bfloat16(v - __bfloat162float(h));
        size_t o = (size_t)(n0 + i) * K + k0 + tx;
        Th[o] = h;
        Tl[o] = l;
    }
}

// ---------------- HMMA bf16 split GEMM --------------------------------------
// C[M,N] = Ahl[M,K] @ Bhl[N,K]^T + bias.  A:[M,K] bf16 h/l, B:[N,K] bf16 h/l.
// CTA 128x128, K chunk 64 halves. smem rows padded to 144B (conflict-free ldsm).
// 8 warps: wm = wid&3 (32 rows each), wn = wid>>2 (64 cols each).
#define RSPAD 144                      // bytes per smem row (128 data + 16 pad)
#define TILE_B (128 * RSPAD)           // 18432 B per tile
#define GEMM_SMEM (4 * TILE_B)         // 73728 B

__global__ void __launch_bounds__(256)
hmma_gemm(const __nv_bfloat16* __restrict__ Ah, const __nv_bfloat16* __restrict__ Al,
          const __nv_bfloat16* __restrict__ Bh, const __nv_bfloat16* __restrict__ Bl,
          const float* __restrict__ bias, float* __restrict__ C, int N) {
    extern __shared__ char smem[];
    const int tid  = threadIdx.x;
    const int wid  = tid >> 5;
    const int lane = tid & 31;
    const int wm   = wid & 3;          // 0..3 -> m offset wm*32
    const int wn   = wid >> 2;         // 0..1 -> n offset wn*64

    const uint32_t sb  = smem_u32(smem);
    const uint32_t sAh = sb;
    const uint32_t sAl = sb + TILE_B;
    const uint32_t sBh = sb + 2 * TILE_B;
    const uint32_t sBl = sb + 3 * TILE_B;

    const int row0 = blockIdx.y * 128;
    const int col0 = blockIdx.x * 128;

    float acc[2][8][4];
    #pragma unroll
    for (int i = 0; i < 2; i++)
        #pragma unroll
        for (int j = 0; j < 8; j++)
            #pragma unroll
            for (int q = 0; q < 4; q++) acc[i][j][q] = 0.0f;

    // ldmatrix source addresses (constant across chunks except kstep offset)
    const uint32_t a_row = wm * 32 + (lane & 15);
    const uint32_t a_koff = (lane >> 4) * 16;          // bytes within row
    const uint32_t b_row = wn * 64 + (lane & 7);
    const uint32_t b_koff = ((lane >> 3) & 1) * 16;    // bytes within row

    for (int c = 0; c < KDIM / 64; c++) {
        const int k0 = c * 64;
        // Stage 4 tiles: each thread cp.asyncs 4 16B chunks per tile.
        #pragma unroll
        for (int i = 0; i < 4; i++) {
            int idx = tid + i * 256;        // 0..1023
            int r = idx >> 3, c16 = idx & 7;
            uint32_t soff = (uint32_t)(r * RSPAD + c16 * 16);
            size_t aoff = (size_t)(row0 + r) * KDIM + k0 + c16 * 8;
            size_t boff = (size_t)(col0 + r) * KDIM + k0 + c16 * 8;
            cp_async16(sAh + soff, Ah + aoff);
            cp_async16(sAl + soff, Al + aoff);
            cp_async16(sBh + soff, Bh + boff);
            cp_async16(sBl + soff, Bl + boff);
        }
        cp_commit_wait();
        __syncthreads();

        #pragma unroll
        for (int ks = 0; ks < 4; ks++) {
            const uint32_t kb = ks * 32;   // byte offset of this k-step
            uint32_t fAh[2][4], fAl[2][4];
            #pragma unroll
            for (int am = 0; am < 2; am++) {
                uint32_t off = (a_row + am * 16) * RSPAD + kb + a_koff;
                ldsm_x4(fAh[am], sAh + off);
                ldsm_x4(fAl[am], sAl + off);
            }
            uint32_t fBh[8][2], fBl[8][2];
            #pragma unroll
            for (int bn = 0; bn < 8; bn++) {
                uint32_t off = (b_row + bn * 8) * RSPAD + kb + b_koff;
                ldsm_x2(fBh[bn], sBh + off);
                ldsm_x2(fBl[bn], sBl + off);
            }
            #pragma unroll
            for (int am = 0; am < 2; am++)
                #pragma unroll
                for (int bn = 0; bn < 8; bn++) {
                    mma_bf16(acc[am][bn], fAh[am], fBh[bn]);
                    mma_bf16(acc[am][bn], fAh[am], fBl[bn]);
                    mma_bf16(acc[am][bn], fAl[am], fBh[bn]);
                }
        }
        __syncthreads();
    }

    // Epilogue: c0/c1 -> (m = lane/4, n = 2*(lane%4)), c2/c3 -> m+8.
    const int mrow = row0 + wm * 32 + (lane >> 2);
    const int ncol0 = col0 + wn * 64 + (lane & 3) * 2;
    #pragma unroll
    for (int am = 0; am < 2; am++) {
        #pragma unroll
        for (int bn = 0; bn < 8; bn++) {
            int col = ncol0 + bn * 8;
            float bx = bias[col], by = bias[col + 1];
            int r0 = mrow + am * 16;
            float2 o0 = {acc[am][bn][0] + bx, acc[am][bn][1] + by};
            float2 o1 = {acc[am][bn][2] + bx, acc[am][bn][3] + by};
            *reinterpret_cast<float2*>(C + (size_t)r0 * N + col) = o0;
            *reinterpret_cast<float2*>(C + (size_t)(r0 + 8) * N + col) = o1;
        }
    }
}

// ---------------- RMSNorm + RoPE --------------------------------------------
__global__ void norm_rope_kernel(float* __restrict__ d,
                                 const float* __restrict__ w,
                                 const float* __restrict__ fcos,
                                 const float* __restrict__ fsin,
                                 int nh) {
    const int gw   = (blockIdx.x * blockDim.x + threadIdx.x) >> 5;
    const int lane = threadIdx.x & 31;
    const int t = gw / nh;
    const int h = gw % nh;

    float* row = d + ((size_t)t * nh + h) * 64;
    float2 xv = reinterpret_cast<float2*>(row)[lane];

    float ss = xv.x * xv.x + xv.y * xv.y;
    #pragma unroll
    for (int off = 16; off; off >>= 1)
        ss += __shfl_xor_sync(0xffffffffu, ss, off);

    float inv = rsqrtf(ss * (1.0f / 64.0f) + 1e-5f);

    float2 wv = reinterpret_cast<const float2*>(w)[lane];
    float a = xv.x * inv * wv.x;
    float b = xv.y * inv * wv.y;

    float c = fcos[t * 32 + lane];
    float s = fsin[t * 32 + lane];

    float2 out;
    out.x = a * c - b * s;
    out.y = a * s + b * c;
    reinterpret_cast<float2*>(row)[lane] = out;
}

// ---------------- flash attention (fp32 SIMT) -------------------------------
__global__ void attn_kernel(const float* __restrict__ q,
                            const float* __restrict__ k,
                            const float* __restrict__ v,
                            float* __restrict__ o) {
    const int qb  = gridDim.x - 1 - blockIdx.x;
    const int h   = blockIdx.y;
    const int kvh = h >> 2;
    const int tid = threadIdx.x;
    const int tr  = tid >> 4;
    const int tc  = tid & 15;

    extern __shared__ float sm[];
    float* Qs = sm;
    float* Ks = sm + 4096;
    float* Vs = sm + 8192;
    float* Ps = sm + 12288;

    const int q0 = qb * 64;

    for (int idx = tid; idx < 4096; idx += 256) {
        int i = idx >> 6;
        int d = idx & 63;
        Qs[d * 64 + i] = q[(size_t)(q0 + i) * (NH * HD) + h * HD + d];
    }

    float m[4], l[4], acc[4][4];
    #pragma unroll
    for (int i = 0; i < 4; i++) {
        m[i] = -1e30f;
        l[i] = 0.0f;
        #pragma unroll
        for (int j = 0; j < 4; j++) acc[i][j] = 0.0f;
    }

    for (int kb = 0; kb <= qb; kb++) {
        const int k0 = kb * 64;
        __syncthreads();
        for (int idx = tid; idx < 4096; idx += 256) {
            int j = idx >> 6;
            int d = idx & 63;
            size_t base = (size_t)(k0 + j) * (NKVH * HD) + kvh * HD + d;
            Ks[d * 64 + j] = k[base];
            Vs[j * 64 + d] = v[base];
        }
        __syncthreads();

        float S[4][4] = {};
        #pragma unroll 16
        for (int d = 0; d < 64; d++) {
            float4 a4 = *reinterpret_cast<const float4*>(&Qs[d * 64 + tr * 4]);
            float4 b4 = *reinterpret_cast<const float4*>(&Ks[d * 64 + tc * 4]);
            float a[4] = {a4.x, a4.y, a4.z, a4.w};
            float b[4] = {b4.x, b4.y, b4.z, b4.w};
            #pragma unroll
            for (int i = 0; i < 4; i++)
                #pragma unroll
                for (int j = 0; j < 4; j++)
                    S[i][j] = fmaf(a[i], b[j], S[i][j]);
        }

        const bool diag = (kb == qb);
        float mi[4];
        #pragma unroll
        for (int i = 0; i < 4; i++) {
            #pragma unroll
            for (int j = 0; j < 4; j++) {
                float s = S[i][j] * 0.125f;
                if (diag && (tc * 4 + j > tr * 4 + i)) s -= 1e9f;
                S[i][j] = s;
            }
            mi[i] = fmaxf(fmaxf(S[i][0], S[i][1]), fmaxf(S[i][2], S[i][3]));
        }
        #pragma unroll
        for (int off = 8; off; off >>= 1)
            #pragma unroll
            for (int i = 0; i < 4; i++)
                mi[i] = fmaxf(mi[i], __shfl_xor_sync(0xffffffffu, mi[i], off));

        float fac[4], rs[4];
        #pragma unroll
        for (int i = 0; i < 4; i++) {
            float mnew = fmaxf(m[i], mi[i]);
            fac[i] = __expf(m[i] - mnew);
            m[i] = mnew;
            float r = 0.0f;
            #pragma unroll
            for (int j = 0; j < 4; j++) {
                float p = __expf(S[i][j] - mnew);
                S[i][j] = p;
                r += p;
            }
            rs[i] = r;
        }
        #pragma unroll
        for (int off = 8; off; off >>= 1)
            #pragma unroll
            for (int i = 0; i < 4; i++)
                rs[i] += __shfl_xor_sync(0xffffffffu, rs[i], off);

        #pragma unroll
        for (int i = 0; i < 4; i++) {
            l[i] = l[i] * fac[i] + rs[i];
            #pragma unroll
            for (int j = 0; j < 4; j++) acc[i][j] *= fac[i];
        }

        #pragma unroll
        for (int j = 0; j < 4; j++)
            #pragma unroll
            for (int i = 0; i < 4; i++)
                Ps[(tc * 4 + j) * 64 + tr * 4 + i] = S[i][j];
        __syncthreads();

        #pragma unroll 16
        for (int j = 0; j < 64; j++) {
            float4 a4 = *reinterpret_cast<const float4*>(&Ps[j * 64 + tr * 4]);
            float4 b4 = *reinterpret_cast<const float4*>(&Vs[j * 64 + tc * 4]);
            float a[4] = {a4.x, a4.y, a4.z, a4.w};
            float b[4] = {b4.x, b4.y, b4.z, b4.w};
            #pragma unroll
            for (int i = 0; i < 4; i++)
                #pragma unroll
                for (int dd = 0; dd < 4; dd++)
                    acc[i][dd] = fmaf(a[i], b[dd], acc[i][dd]);
        }
    }

    #pragma unroll
    for (int i = 0; i < 4; i++) {
        float invl = 1.0f / l[i];
        size_t rbase = (size_t)(q0 + tr * 4 + i) * (NH * HD) + h * HD + tc * 4;
        #pragma unroll
        for (int dd = 0; dd < 4; dd++)
            o[rbase + dd] = acc[i][dd] * invl;
    }
}

// ---------------------------------------------------------------------------
extern "C" void kernel_launch(void* const* d_in, const int* in_sizes, int n_in,
                              void* d_out, int out_size) {
    const float* x    = (const float*)d_in[0];
    const float* fcos = (const float*)d_in[1];
    const float* fsin = (const float*)d_in[2];
    const float* wq  = (const float*)d_in[4];
    const float* wqb = (const float*)d_in[5];
    const float* wk  = (const float*)d_in[6];
    const float* wkb = (const float*)d_in[7];
    const float* wv  = (const float*)d_in[8];
    const float* wvb = (const float*)d_in[9];
    const float* wo  = (const float*)d_in[10];
    const float* wob = (const float*)d_in[11];
    const float* qnw = (const float*)d_in[12];
    const float* knw = (const float*)d_in[13];
    float* out = (float*)d_out;

    float *q, *k, *v, *att;
    cudaGetSymbolAddress((void**)&q,   g_q);
    cudaGetSymbolAddress((void**)&k,   g_k);
    cudaGetSymbolAddress((void**)&v,   g_v);
    cudaGetSymbolAddress((void**)&att, g_att);

    __nv_bfloat16 *xh, *xl, *ah, *al, *wqh, *wql, *wkh, *wkl, *wvh, *wvl, *woh, *wol;
    cudaGetSymbolAddress((void**)&xh,  g_xh);
    cudaGetSymbolAddress((void**)&xl,  g_xl);
    cudaGetSymbolAddress((void**)&ah,  g_ah);
    cudaGetSymbolAddress((void**)&al,  g_al);
    cudaGetSymbolAddress((void**)&wqh, g_wqh);
    cudaGetSymbolAddress((void**)&wql, g_wql);
    cudaGetSymbolAddress((void**)&wkh, g_wkh);
    cudaGetSymbolAddress((void**)&wkl, g_wkl);
    cudaGetSymbolAddress((void**)&wvh, g_wvh);
    cudaGetSymbolAddress((void**)&wvl, g_wvl);
    cudaGetSymbolAddress((void**)&woh, g_woh);
    cudaGetSymbolAddress((void**)&wol, g_wol);

    cudaFuncSetAttribute(hmma_gemm, cudaFuncAttributeMaxDynamicSharedMemorySize, GEMM_SMEM);
    cudaFuncSetAttribute(attn_kernel, cudaFuncAttributeMaxDynamicSharedMemorySize, 65536);

    // Split inputs / transpose+split weights to bf16 hi/lo
    split_ew<<<(TT * CC / 4 + 255) / 256, 256>>>(x, xh, xl, TT * CC / 4);
    transpose_split<<<dim3(CC / 32, CC / 32), dim3(32, 8)>>>(wq, wqh, wql, CC, CC);
    transpose_split<<<dim3(512 / 32, CC / 32), dim3(32, 8)>>>(wk, wkh, wkl, CC, 512);
    transpose_split<<<dim3(512 / 32, CC / 32), dim3(32, 8)>>>(wv, wvh, wvl, CC, 512);
    transpose_split<<<dim3(CC / 32, CC / 32), dim3(32, 8)>>>(wo, woh, wol, CC, CC);

    // QKV projections on tensor cores (HMMA)
    hmma_gemm<<<dim3(CC / 128, TT / 128), 256, GEMM_SMEM>>>(xh, xl, wqh, wql, wqb, q, CC);
    hmma_gemm<<<dim3(512 / 128, TT / 128), 256, GEMM_SMEM>>>(xh, xl, wkh, wkl, wkb, k, 512);
    hmma_gemm<<<dim3(512 / 128, TT / 128), 256, GEMM_SMEM>>>(xh, xl, wvh, wvl, wvb, v, 512);

    // RMSNorm + RoPE
    norm_rope_kernel<<<(TT * NH) / 8, 256>>>(q, qnw, fcos, fsin, NH);
    norm_rope_kernel<<<(TT * NKVH) / 8, 256>>>(k, knw, fcos, fsin, NKVH);

    // Attention (fp32 SIMT)
    attn_kernel<<<dim3(TT / 64, NH), 256, 65536>>>(q, k, v, att);

    // Output projection on tensor cores (HMMA)
    split_ew<<<(TT * CC / 4 + 255) / 256, 256>>>(att, ah, al, TT * CC / 4);
    hmma_gemm<<<dim3(CC / 128, TT / 128), 256, GEMM_SMEM>>>(ah, al, woh, wol, wob, out, CC);
}

// round 11
// speedup vs baseline: 3.0912x; 1.8866x over previous
#include <cuda_runtime.h>
#include <cuda_bf16.h>
#include <stdint.h>
#include <math.h>

#define TT 2048
#define CC 2048
#define NH 32
#define NKVH 8
#define HD 64
#define KDIM 2048

// ---------------- scratch (device globals; no allocation allowed) ----------
__device__ float g_q[TT * CC];
__device__ float g_k[TT * NKVH * HD];
__device__ float g_v[TT * NKVH * HD];
__device__ float g_att[TT * CC];

__device__ __nv_bfloat16 g_xh[TT * CC],  g_xl[TT * CC];
__device__ __nv_bfloat16 g_ah[TT * CC],  g_al[TT * CC];
__device__ __nv_bfloat16 g_wqh[CC * CC], g_wql[CC * CC];
__device__ __nv_bfloat16 g_wkh[512 * CC], g_wkl[512 * CC];
__device__ __nv_bfloat16 g_wvh[512 * CC], g_wvl[512 * CC];
__device__ __nv_bfloat16 g_woh[CC * CC], g_wol[CC * CC];
// attention bf16 operands
__device__ __nv_bfloat16 g_qh[TT * CC],  g_ql[TT * CC];
__device__ __nv_bfloat16 g_kh[TT * 512], g_kl[TT * 512];
__device__ __nv_bfloat16 g_vth[512 * TT], g_vtl[512 * TT];   // [kvh*64+d][t]

// ---------------- helpers ----------------------------------------------
__device__ __forceinline__ uint32_t smem_u32(const void* p) {
    uint32_t a;
    asm("{ .reg .u64 t; cvta.to.shared.u64 t, %1; cvt.u32.u64 %0, t; }" : "=r"(a) : "l"(p));
    return a;
}
__device__ __forceinline__ void cp_async16(uint32_t s, const void* g) {
    asm volatile("cp.async.cg.shared.global [%0], [%1], 16;" :: "r"(s), "l"(g) : "memory");
}
__device__ __forceinline__ void cp_commit_wait() {
    asm volatile("cp.async.commit_group;" ::: "memory");
    asm volatile("cp.async.wait_group 0;" ::: "memory");
}
__device__ __forceinline__ void ldsm_x4(uint32_t* r, uint32_t a) {
    asm volatile("ldmatrix.sync.aligned.m8n8.x4.shared.b16 {%0,%1,%2,%3}, [%4];"
                 : "=r"(r[0]), "=r"(r[1]), "=r"(r[2]), "=r"(r[3]) : "r"(a));
}
__device__ __forceinline__ void ldsm_x2(uint32_t* r, uint32_t a) {
    asm volatile("ldmatrix.sync.aligned.m8n8.x2.shared.b16 {%0,%1}, [%2];"
                 : "=r"(r[0]), "=r"(r[1]) : "r"(a));
}
__device__ __forceinline__ void mma_bf16(float* d, const uint32_t* a, const uint32_t* b) {
    asm volatile(
        "mma.sync.aligned.m16n8k16.row.col.f32.bf16.bf16.f32 "
        "{%0,%1,%2,%3}, {%4,%5,%6,%7}, {%8,%9}, {%0,%1,%2,%3};"
        : "+f"(d[0]), "+f"(d[1]), "+f"(d[2]), "+f"(d[3])
        : "r"(a[0]), "r"(a[1]), "r"(a[2]), "r"(a[3]), "r"(b[0]), "r"(b[1]));
}
// FFMA-only expf (rel err ~3e-5); clamped so -1e30 masked scores -> 0
__device__ __forceinline__ float fast_exp(float x) {
    x = fmaxf(x, -87.0f);
    float y = x * 1.4426950408889634f;
    float r = rintf(y);
    float f = y - r;
    float p = 1.0f + f * (0.6931471805599453f + f * (0.2402265069591007f +
              f * (0.05550410866482158f + f * 0.009618129107628477f)));
    return __int_as_float(__float_as_int(p) + (((int)r) << 23));
}
// hi/lo bf16x2 pack of two floats
__device__ __forceinline__ void hilo2(float a, float b, uint32_t& h, uint32_t& l) {
    __nv_bfloat16 ha = __float2bfloat16(a), hb = __float2bfloat16(b);
    float ra = a - __bfloat162float(ha), rb = b - __bfloat162float(hb);
    __nv_bfloat162 H; H.x = ha; H.y = hb;
    __nv_bfloat162 L = __floats2bfloat162_rn(ra, rb);
    h = *reinterpret_cast<uint32_t*>(&H);
    l = *reinterpret_cast<uint32_t*>(&L);
}

// ---------------- split kernels ---------------------------------------------
struct alignas(8) bf4 { __nv_bfloat16 v[4]; };

__global__ void split_ew(const float* __restrict__ x, __nv_bfloat16* __restrict__ h,
                         __nv_bfloat16* __restrict__ l, int n4) {
    int i = blockIdx.x * blockDim.x + threadIdx.x;
    if (i >= n4) return;
    float4 v = reinterpret_cast<const float4*>(x)[i];
    float f[4] = {v.x, v.y, v.z, v.w};
    bf4 hh, ll;
    #pragma unroll
    for (int j = 0; j < 4; j++) {
        hh.v[j] = __float2bfloat16(f[j]);
        ll.v[j] = __float2bfloat16(f[j] - __bfloat162float(hh.v[j]));
    }
    reinterpret_cast<bf4*>(h)[i] = hh;
    reinterpret_cast<bf4*>(l)[i] = ll;
}

// W [K,N] fp32 -> Th/Tl [N,K] bf16
__global__ void transpose_split(const float* __restrict__ W, __nv_bfloat16* __restrict__ Th,
                                __nv_bfloat16* __restrict__ Tl, int K, int N) {
    __shared__ float t[32][33];
    int n0 = blockIdx.x * 32, k0 = blockIdx.y * 32;
    int tx = threadIdx.x, ty = threadIdx.y;   // (32, 8)
    #pragma unroll
    for (int i = ty; i < 32; i += 8)
        t[i][tx] = W[(size_t)(k0 + i) * N + n0 + tx];
    __syncthreads();
    #pragma unroll
    for (int i = ty; i < 32; i += 8) {
        float v = t[tx][i];
        __nv_bfloat16 h = __float2bfloat16(v);
        __nv_bfloat16 l = __float2bfloat16(v - __bfloat162float(h));
        size_t o = (size_t)(n0 + i) * K + k0 + tx;
        Th[o] = h;
        Tl[o] = l;
    }
}

// ---------------- HMMA bf16 split GEMM --------------------------------------
#define RSPAD 144
#define TILE_B (128 * RSPAD)
#define GEMM_SMEM (4 * TILE_B)

__global__ void __launch_bounds__(256)
hmma_gemm(const __nv_bfloat16* __restrict__ Ah, const __nv_bfloat16* __restrict__ Al,
          const __nv_bfloat16* __restrict__ Bh, const __nv_bfloat16* __restrict__ Bl,
          const float* __restrict__ bias, float* __restrict__ C, int N) {
    extern __shared__ char smem[];
    const int tid  = threadIdx.x;
    const int wid  = tid >> 5;
    const int lane = tid & 31;
    const int wm   = wid & 3;
    const int wn   = wid >> 2;

    const uint32_t sb  = smem_u32(smem);
    const uint32_t sAh = sb;
    const uint32_t sAl = sb + TILE_B;
    const uint32_t sBh = sb + 2 * TILE_B;
    const uint32_t sBl = sb + 3 * TILE_B;

    const int row0 = blockIdx.y * 128;
    const int col0 = blockIdx.x * 128;

    float acc[2][8][4];
    #pragma unroll
    for (int i = 0; i < 2; i++)
        #pragma unroll
        for (int j = 0; j < 8; j++)
            #pragma unroll
            for (int q = 0; q < 4; q++) acc[i][j][q] = 0.0f;

    const uint32_t a_row = wm * 32 + (lane & 15);
    const uint32_t a_koff = (lane >> 4) * 16;
    const uint32_t b_row = wn * 64 + (lane & 7);
    const uint32_t b_koff = ((lane >> 3) & 1) * 16;

    for (int c = 0; c < KDIM / 64; c++) {
        const int k0 = c * 64;
        #pragma unroll
        for (int i = 0; i < 4; i++) {
            int idx = tid + i * 256;
            int r = idx >> 3, c16 = idx & 7;
            uint32_t soff = (uint32_t)(r * RSPAD + c16 * 16);
            size_t aoff = (size_t)(row0 + r) * KDIM + k0 + c16 * 8;
            size_t boff = (size_t)(col0 + r) * KDIM + k0 + c16 * 8;
            cp_async16(sAh + soff, Ah + aoff);
            cp_async16(sAl + soff, Al + aoff);
            cp_async16(sBh + soff, Bh + boff);
            cp_async16(sBl + soff, Bl + boff);
        }
        cp_commit_wait();
        __syncthreads();

        #pragma unroll
        for (int ks = 0; ks < 4; ks++) {
            const uint32_t kb = ks * 32;
            uint32_t fAh[2][4], fAl[2][4];
            #pragma unroll
            for (int am = 0; am < 2; am++) {
                uint32_t off = (a_row + am * 16) * RSPAD + kb + a_koff;
                ldsm_x4(fAh[am], sAh + off);
                ldsm_x4(fAl[am], sAl + off);
            }
            uint32_t fBh[8][2], fBl[8][2];
            #pragma unroll
            for (int bn = 0; bn < 8; bn++) {
                uint32_t off = (b_row + bn * 8) * RSPAD + kb + b_koff;
                ldsm_x2(fBh[bn], sBh + off);
                ldsm_x2(fBl[bn], sBl + off);
            }
            #pragma unroll
            for (int am = 0; am < 2; am++)
                #pragma unroll
                for (int bn = 0; bn < 8; bn++) {
                    mma_bf16(acc[am][bn], fAh[am], fBh[bn]);
                    mma_bf16(acc[am][bn], fAh[am], fBl[bn]);
                    mma_bf16(acc[am][bn], fAl[am], fBh[bn]);
                }
        }
        __syncthreads();
    }

    const int mrow = row0 + wm * 32 + (lane >> 2);
    const int ncol0 = col0 + wn * 64 + (lane & 3) * 2;
    #pragma unroll
    for (int am = 0; am < 2; am++) {
        #pragma unroll
        for (int bn = 0; bn < 8; bn++) {
            int col = ncol0 + bn * 8;
            float bx = bias[col], by = bias[col + 1];
            int r0 = mrow + am * 16;
            float2 o0 = {acc[am][bn][0] + bx, acc[am][bn][1] + by};
            float2 o1 = {acc[am][bn][2] + bx, acc[am][bn][3] + by};
            *reinterpret_cast<float2*>(C + (size_t)r0 * N + col) = o0;
            *reinterpret_cast<float2*>(C + (size_t)(r0 + 8) * N + col) = o1;
        }
    }
}

// ---------------- RMSNorm + RoPE --------------------------------------------
__global__ void norm_rope_kernel(float* __restrict__ d,
                                 const float* __restrict__ w,
                                 const float* __restrict__ fcos,
                                 const float* __restrict__ fsin,
                                 int nh) {
    const int gw   = (blockIdx.x * blockDim.x + threadIdx.x) >> 5;
    const int lane = threadIdx.x & 31;
    const int t = gw / nh;
    const int h = gw % nh;

    float* row = d + ((size_t)t * nh + h) * 64;
    float2 xv = reinterpret_cast<float2*>(row)[lane];

    float ss = xv.x * xv.x + xv.y * xv.y;
    #pragma unroll
    for (int off = 16; off; off >>= 1)
        ss += __shfl_xor_sync(0xffffffffu, ss, off);

    float inv = rsqrtf(ss * (1.0f / 64.0f) + 1e-5f);

    float2 wv = reinterpret_cast<const float2*>(w)[lane];
    float a = xv.x * inv * wv.x;
    float b = xv.y * inv * wv.y;

    float c = fcos[t * 32 + lane];
    float s = fsin[t * 32 + lane];

    float2 out;
    out.x = a * c - b * s;
    out.y = a * s + b * c;
    reinterpret_cast<float2*>(row)[lane] = out;
}

// ---------------- HMMA flash attention --------------------------------------
// 128 threads (4 warps). CTA = (64-query block) x head. Warp w owns rows w*16..+16.
// Q,K tiles [64 x 64] bf16 hi/lo; V transposed [64 d x 64 key] bf16 hi/lo.
// S fragments feed PV directly as A fragments (no smem roundtrip).
#define ARS 144
#define ATILE (64 * ARS)               // 9216 B
#define ATTN_SMEM (6 * ATILE)          // 55296 B

__global__ void __launch_bounds__(128)
attn_mma(const __nv_bfloat16* __restrict__ qh, const __nv_bfloat16* __restrict__ ql,
         const __nv_bfloat16* __restrict__ kh, const __nv_bfloat16* __restrict__ kl,
         const __nv_bfloat16* __restrict__ vth, const __nv_bfloat16* __restrict__ vtl,
         float* __restrict__ o) {
    const int qb  = gridDim.x - 1 - blockIdx.x;   // long blocks first
    const int h   = blockIdx.y;
    const int kvh = h >> 2;
    const int tid = threadIdx.x;
    const int wid = tid >> 5;
    const int lane = tid & 31;
    const int q0 = qb * 64;

    extern __shared__ char smem[];
    const uint32_t sb  = smem_u32(smem);
    const uint32_t sQh = sb,             sQl = sb + ATILE;
    const uint32_t sKh = sb + 2 * ATILE, sKl = sb + 3 * ATILE;
    const uint32_t sVh = sb + 4 * ATILE, sVl = sb + 5 * ATILE;

    // Load Q tile (64 rows x 128B), hi+lo
    #pragma unroll
    for (int i = 0; i < 4; i++) {
        int idx = tid + i * 128;
        int r = idx >> 3, c16 = idx & 7;
        uint32_t soff = (uint32_t)(r * ARS + c16 * 16);
        size_t goff = (size_t)(q0 + r) * CC + h * HD + c16 * 8;
        cp_async16(sQh + soff, qh + goff);
        cp_async16(sQl + soff, ql + goff);
    }
    cp_commit_wait();
    __syncthreads();

    // fragment addressing
    const uint32_t a_off  = (uint32_t)((wid * 16 + (lane & 15)) * ARS + (lane >> 4) * 16);
    const uint32_t b_base = (uint32_t)((lane & 7) * ARS + ((lane >> 3) & 1) * 16);

    float m0 = -1e30f, m1 = -1e30f, l0 = 0.0f, l1 = 0.0f;
    float O[8][4];
    #pragma unroll
    for (int nt = 0; nt < 8; nt++)
        #pragma unroll
        for (int j = 0; j < 4; j++) O[nt][j] = 0.0f;

    const int row0 = q0 + wid * 16 + (lane >> 2);   // thread's first query row
    const int row1 = row0 + 8;

    for (int kb = 0; kb <= qb; kb++) {
        const int k0 = kb * 64;
        __syncthreads();
        // load K, Vt tiles hi/lo
        #pragma unroll
        for (int i = 0; i < 4; i++) {
            int idx = tid + i * 128;
            int r = idx >> 3, c16 = idx & 7;
            uint32_t soff = (uint32_t)(r * ARS + c16 * 16);
            size_t kg = (size_t)(k0 + r) * 512 + kvh * HD + c16 * 8;
            size_t vg = (size_t)(kvh * HD + r) * TT + k0 + c16 * 8;
            cp_async16(sKh + soff, kh + kg);
            cp_async16(sKl + soff, kl + kg);
            cp_async16(sVh + soff, vth + vg);
            cp_async16(sVl + soff, vtl + vg);
        }
        cp_commit_wait();
        __syncthreads();

        // ---- S = Q K^T (hi/lo: 3 MMAs) ----
        float S[8][4];
        #pragma unroll
        for (int nt = 0; nt < 8; nt++)
            #pragma unroll
            for (int j = 0; j < 4; j++) S[nt][j] = 0.0f;

        #pragma unroll
        for (int ks = 0; ks < 4; ks++) {
            const uint32_t kbyte = ks * 32;
            uint32_t fQh[4], fQl[4];
            ldsm_x4(fQh, sQh + a_off + kbyte);
            ldsm_x4(fQl, sQl + a_off + kbyte);
            #pragma unroll
            for (int nt = 0; nt < 8; nt++) {
                uint32_t fKh[2], fKl[2];
                uint32_t boff = b_base + (uint32_t)(nt * 8 * ARS) + kbyte;
                ldsm_x2(fKh, sKh + boff);
                ldsm_x2(fKl, sKl + boff);
                mma_bf16(S[nt], fQh, fKh);
                mma_bf16(S[nt], fQh, fKl);
                mma_bf16(S[nt], fQl, fKh);
            }
        }

        // ---- scale + causal mask ----
        const bool diag = (kb == qb);
        #pragma unroll
        for (int nt = 0; nt < 8; nt++) {
            int colb = k0 + nt * 8 + ((lane & 3) << 1);
            #pragma unroll
            for (int j = 0; j < 4; j++) {
                float s = S[nt][j] * 0.125f;
                if (diag) {
                    int col = colb + (j & 1);
                    int row = (j < 2) ? row0 : row1;
                    if (col > row) s = -1e30f;
                }
                S[nt][j] = s;
            }
        }

        // ---- online softmax (rows: row0 uses j 0..1, row1 uses j 2..3) ----
        float mx0 = -1e30f, mx1 = -1e30f;
        #pragma unroll
        for (int nt = 0; nt < 8; nt++) {
            mx0 = fmaxf(mx0, fmaxf(S[nt][0], S[nt][1]));
            mx1 = fmaxf(mx1, fmaxf(S[nt][2], S[nt][3]));
        }
        mx0 = fmaxf(mx0, __shfl_xor_sync(0xffffffffu, mx0, 1));
        mx0 = fmaxf(mx0, __shfl_xor_sync(0xffffffffu, mx0, 2));
        mx1 = fmaxf(mx1, __shfl_xor_sync(0xffffffffu, mx1, 1));
        mx1 = fmaxf(mx1, __shfl_xor_sync(0xffffffffu, mx1, 2));

        float mn0 = fmaxf(m0, mx0), mn1 = fmaxf(m1, mx1);
        float fac0 = fast_exp(m0 - mn0), fac1 = fast_exp(m1 - mn1);
        m0 = mn0; m1 = mn1;

        float rs0 = 0.0f, rs1 = 0.0f;
        #pragma unroll
        for (int nt = 0; nt < 8; nt++) {
            S[nt][0] = fast_exp(S[nt][0] - mn0); rs0 += S[nt][0];
            S[nt][1] = fast_exp(S[nt][1] - mn0); rs0 += S[nt][1];
            S[nt][2] = fast_exp(S[nt][2] - mn1); rs1 += S[nt][2];
            S[nt][3] = fast_exp(S[nt][3] - mn1); rs1 += S[nt][3];
        }
        rs0 += __shfl_xor_sync(0xffffffffu, rs0, 1);
        rs0 += __shfl_xor_sync(0xffffffffu, rs0, 2);
        rs1 += __shfl_xor_sync(0xffffffffu, rs1, 1);
        rs1 += __shfl_xor_sync(0xffffffffu, rs1, 2);
        l0 = l0 * fac0 + rs0;
        l1 = l1 * fac1 + rs1;

        #pragma unroll
        for (int nt = 0; nt < 8; nt++) {
            O[nt][0] *= fac0; O[nt][1] *= fac0;
            O[nt][2] *= fac1; O[nt][3] *= fac1;
        }

        // ---- O += P V  (P from S fragments, hi/lo; V hi/lo) ----
        #pragma unroll
        for (int ks = 0; ks < 4; ks++) {
            const int t0 = 2 * ks, t1 = t0 + 1;
            uint32_t aH[4], aL[4];
            hilo2(S[t0][0], S[t0][1], aH[0], aL[0]);
            hilo2(S[t0][2], S[t0][3], aH[1], aL[1]);
            hilo2(S[t1][0], S[t1][1], aH[2], aL[2]);
            hilo2(S[t1][2], S[t1][3], aH[3], aL[3]);
            const uint32_t kbyte = ks * 32;
            #pragma unroll
            for (int nt = 0; nt < 8; nt++) {
                uint32_t fVh[2], fVl[2];
                uint32_t boff = b_base + (uint32_t)(nt * 8 * ARS) + kbyte;
                ldsm_x2(fVh, sVh + boff);
                ldsm_x2(fVl, sVl + boff);
                mma_bf16(O[nt], aH, fVh);
                mma_bf16(O[nt], aH, fVl);
                mma_bf16(O[nt], aL, fVh);
            }
        }
    }

    // epilogue
    float il0 = 1.0f / l0, il1 = 1.0f / l1;
    #pragma unroll
    for (int nt = 0; nt < 8; nt++) {
        int d0 = h * HD + nt * 8 + ((lane & 3) << 1);
        float2 o0 = {O[nt][0] * il0, O[nt][1] * il0};
        float2 o1 = {O[nt][2] * il1, O[nt][3] * il1};
        *reinterpret_cast<float2*>(o + (size_t)row0 * CC + d0) = o0;
        *reinterpret_cast<float2*>(o + (size_t)row1 * CC + d0) = o1;
    }
}

// ---------------------------------------------------------------------------
extern "C" void kernel_launch(void* const* d_in, const int* in_sizes, int n_in,
                              void* d_out, int out_size) {
    const float* x    = (const float*)d_in[0];
    const float* fcos = (const float*)d_in[1];
    const float* fsin = (const float*)d_in[2];
    const float* wq  = (const float*)d_in[4];
    const float* wqb = (const float*)d_in[5];
    const float* wk  = (const float*)d_in[6];
    const float* wkb = (const float*)d_in[7];
    const float* wv  = (const float*)d_in[8];
    const float* wvb = (const float*)d_in[9];
    const float* wo  = (const float*)d_in[10];
    const float* wob = (const float*)d_in[11];
    const float* qnw = (const float*)d_in[12];
    const float* knw = (const float*)d_in[13];
    float* out = (float*)d_out;

    float *q, *k, *v, *att;
    cudaGetSymbolAddress((void**)&q,   g_q);
    cudaGetSymbolAddress((void**)&k,   g_k);
    cudaGetSymbolAddress((void**)&v,   g_v);
    cudaGetSymbolAddress((void**)&att, g_att);

    __nv_bfloat16 *xh, *xl, *ah, *al, *wqh, *wql, *wkh, *wkl, *wvh, *wvl, *woh, *wol;
    __nv_bfloat16 *qh, *ql, *khp, *klp, *vth, *vtl;
    cudaGetSymbolAddress((void**)&xh,  g_xh);
    cudaGetSymbolAddress((void**)&xl,  g_xl);
    cudaGetSymbolAddress((void**)&ah,  g_ah);
    cudaGetSymbolAddress((void**)&al,  g_al);
    cudaGetSymbolAddress((void**)&wqh, g_wqh);
    cudaGetSymbolAddress((void**)&wql, g_wql);
    cudaGetSymbolAddress((void**)&wkh, g_wkh);
    cudaGetSymbolAddress((void**)&wkl, g_wkl);
    cudaGetSymbolAddress((void**)&wvh, g_wvh);
    cudaGetSymbolAddress((void**)&wvl, g_wvl);
    cudaGetSymbolAddress((void**)&woh, g_woh);
    cudaGetSymbolAddress((void**)&wol, g_wol);
    cudaGetSymbolAddress((void**)&qh,  g_qh);
    cudaGetSymbolAddress((void**)&ql,  g_ql);
    cudaGetSymbolAddress((void**)&khp, g_kh);
    cudaGetSymbolAddress((void**)&klp, g_kl);
    cudaGetSymbolAddress((void**)&vth, g_vth);
    cudaGetSymbolAddress((void**)&vtl, g_vtl);

    cudaFuncSetAttribute(hmma_gemm, cudaFuncAttributeMaxDynamicSharedMemorySize, GEMM_SMEM);
    cudaFuncSetAttribute(attn_mma, cudaFuncAttributeMaxDynamicSharedMemorySize, ATTN_SMEM);

    // Split inputs / transpose+split weights to bf16 hi/lo
    split_ew<<<(TT * CC / 4 + 255) / 256, 256>>>(x, xh, xl, TT * CC / 4);
    transpose_split<<<dim3(CC / 32, CC / 32), dim3(32, 8)>>>(wq, wqh, wql, CC, CC);
    transpose_split<<<dim3(512 / 32, CC / 32), dim3(32, 8)>>>(wk, wkh, wkl, CC, 512);
    transpose_split<<<dim3(512 / 32, CC / 32), dim3(32, 8)>>>(wv, wvh, wvl, CC, 512);
    transpose_split<<<dim3(CC / 32, CC / 32), dim3(32, 8)>>>(wo, woh, wol, CC, CC);

    // QKV projections on tensor cores (HMMA)
    hmma_gemm<<<dim3(CC / 128, TT / 128), 256, GEMM_SMEM>>>(xh, xl, wqh, wql, wqb, q, CC);
    hmma_gemm<<<dim3(512 / 128, TT / 128), 256, GEMM_SMEM>>>(xh, xl, wkh, wkl, wkb, k, 512);
    hmma_gemm<<<dim3(512 / 128, TT / 128), 256, GEMM_SMEM>>>(xh, xl, wvh, wvl, wvb, v, 512);

    // RMSNorm + RoPE
    norm_rope_kernel<<<(TT * NH) / 8, 256>>>(q, qnw, fcos, fsin, NH);
    norm_rope_kernel<<<(TT * NKVH) / 8, 256>>>(k, knw, fcos, fsin, NKVH);

    // Convert attention operands to bf16 hi/lo; V transposed to [kvh*64+d][t]
    split_ew<<<(TT * CC / 4 + 255) / 256, 256>>>(q, qh, ql, TT * CC / 4);
    split_ew<<<(TT * 512 / 4 + 255) / 256, 256>>>(k, khp, klp, TT * 512 / 4);
    transpose_split<<<dim3(512 / 32, TT / 32), dim3(32, 8)>>>(v, vth, vtl, TT, 512);

    // Attention (HMMA flash)
    attn_mma<<<dim3(TT / 64, NH), 128, ATTN_SMEM>>>(qh, ql, khp, klp, vth, vtl, att);

    // Output projection on tensor cores (HMMA)
    split_ew<<<(TT * CC / 4 + 255) / 256, 256>>>(att, ah, al, TT * CC / 4);
    hmma_gemm<<<dim3(CC / 128, TT / 128), 256, GEMM_SMEM>>>(ah, al, woh, wol, wob, out, CC);
}